// round 16
// baseline (speedup 1.0000x reference)
#include <cuda_runtime.h>
#include <cuda_bf16.h>
#include <cuda_fp16.h>
#include <math.h>

#define B_ 16
#define N_ 512
#define H_ 8
#define E_ 128
#define BH_ (B_*H_)
#define SCALE_ 0.08838834764831845f
#define LOG2E_ 1.4426950408889634f
#define QSCALE_ (SCALE_ * LOG2E_)
#define DNEG_ (-30000.0f)

// fp16 packed (u32 = h2) arrays
__device__ unsigned g_x16[B_*N_*E_/2];
__device__ unsigned g_wq16[1024*E_/2];
__device__ unsigned g_wk16[1024*E_/2];
__device__ unsigned g_wv16[1024*E_/2];
__device__ unsigned g_wo16[E_*1024/2];
__device__ unsigned g_q16[BH_*N_*E_/2];
__device__ unsigned g_k16[BH_*N_*E_/2];
__device__ unsigned g_v16[BH_*N_*E_/2];
__device__ unsigned g_y16[BH_*N_*E_/2];
__device__ unsigned g_d16[B_*N_*N_/2];

// ---------------------------------------------------------------------------
// helpers
// ---------------------------------------------------------------------------
__device__ __forceinline__ unsigned smem_u32(const void* p) {
    unsigned r;
    asm("{ .reg .u64 t; cvta.to.shared.u64 t, %1; cvt.u32.u64 %0, t; }" : "=r"(r) : "l"(p));
    return r;
}
__device__ __forceinline__ void ldsm4(unsigned r[4], unsigned addr) {
    asm volatile("ldmatrix.sync.aligned.m8n8.x4.shared.b16 {%0,%1,%2,%3}, [%4];"
        : "=r"(r[0]), "=r"(r[1]), "=r"(r[2]), "=r"(r[3]) : "r"(addr));
}
__device__ __forceinline__ void ldsm4t(unsigned r[4], unsigned addr) {
    asm volatile("ldmatrix.sync.aligned.m8n8.x4.trans.shared.b16 {%0,%1,%2,%3}, [%4];"
        : "=r"(r[0]), "=r"(r[1]), "=r"(r[2]), "=r"(r[3]) : "r"(addr));
}
__device__ __forceinline__ void mma_f16(float c[4], const unsigned a[4],
                                        unsigned b0, unsigned b1) {
    asm volatile("mma.sync.aligned.m16n8k16.row.col.f32.f16.f16.f32 "
        "{%0,%1,%2,%3}, {%4,%5,%6,%7}, {%8,%9}, {%0,%1,%2,%3};"
        : "+f"(c[0]), "+f"(c[1]), "+f"(c[2]), "+f"(c[3])
        : "r"(a[0]), "r"(a[1]), "r"(a[2]), "r"(a[3]), "r"(b0), "r"(b1));
}
__device__ __forceinline__ unsigned pack_h2(float a, float b) {
    __half2 h = __floats2half2_rn(a, b);
    return *(unsigned*)&h;
}
__device__ __forceinline__ float ex2f(float x) {
    float r;
    asm("ex2.approx.f32 %0, %1;" : "=f"(r) : "f"(x));
    return r;
}

#define CP16(dst, src) \
    asm volatile("cp.async.cg.shared.global [%0], [%1], 16;" \
        :: "r"(dst), "l"(__cvta_generic_to_global(src)) : "memory")
#define CP_COMMIT asm volatile("cp.async.commit_group;" ::: "memory")
#define CP_WAIT0  asm volatile("cp.async.wait_group 0;" ::: "memory")
#define CP_WAIT1  asm volatile("cp.async.wait_group 1;" ::: "memory")

// packed-fp16 tile async copy: global (row stride 64 u32) -> smem 272B stride
__device__ __forceinline__ void copy16_async(const unsigned* __restrict__ src,
        unsigned sb, int off, int rows, int tid, int nthr)
{
    const int total = rows * 16;
    for (int idx = tid; idx < total; idx += nthr) {
        int r = idx >> 4, c = idx & 15;
        CP16(sb + off + r * 272 + c * 16, src + (size_t)r * 64 + c * 4);
    }
}

// ---------------------------------------------------------------------------
// Kernel 0: convert all fp32 inputs to fp16 (unchanged).
// ---------------------------------------------------------------------------
__global__ __launch_bounds__(256) void prep_kernel(
    const float* __restrict__ x,
    const float* __restrict__ Wq, const float* __restrict__ Wk,
    const float* __restrict__ Wv, const float* __restrict__ Wo,
    const float* __restrict__ dist, const float* __restrict__ mask)
{
    const int flat = blockIdx.x * 256 + threadIdx.x;

    #pragma unroll
    for (int j = 0; j < 4; j++) {
        int i = flat + j * 131072;
        float2 v = *(const float2*)(x + 2 * (size_t)i);
        g_x16[i] = pack_h2(v.x, v.y);
    }
    if (flat < 65536) {
        float2 vq = *(const float2*)(Wq + 2 * flat);
        float2 vk = *(const float2*)(Wk + 2 * flat);
        float2 vv = *(const float2*)(Wv + 2 * flat);
        float2 vo = *(const float2*)(Wo + 2 * flat);
        g_wq16[flat] = pack_h2(vq.x, vq.y);
        g_wk16[flat] = pack_h2(vk.x, vk.y);
        g_wv16[flat] = pack_h2(vv.x, vv.y);
        g_wo16[flat] = pack_h2(vo.x, vo.y);
    }
    #pragma unroll
    for (int j = 0; j < 16; j++) {
        int i = flat + j * 131072;
        float2 v = *(const float2*)(dist + 2 * (size_t)i);
        int k0 = (2 * i) & 511;
        int row = i >> 8;
        int b = row >> 9;
        float m0 = mask[b * 512 + k0], m1 = mask[b * 512 + k0 + 1];
        g_d16[i] = pack_h2((m0 != 0.f) ? v.x * LOG2E_ : DNEG_,
                           (m1 != 0.f) ? v.y * LOG2E_ : DNEG_);
    }
}

// ---------------------------------------------------------------------------
// Kernel 1: QKV projection. ONE CTA computes q,k,v for its (row,col) tile.
// X loaded once; W cycled through a double-buffered slot. 512 CTAs, 2/SM.
// ---------------------------------------------------------------------------
#define QM_X  0
#define QM_W0 34816
#define QM_W1 69632
#define SMEM_QKV 104448

__global__ __launch_bounds__(256, 2) void qkv_mma_kernel(
    const float* __restrict__ bq, const float* __restrict__ bk,
    const float* __restrict__ bv)
{
    extern __shared__ char smc[];
    const unsigned sb = smem_u32(smc);

    const int tid  = threadIdx.x;
    const int lane = tid & 31;
    const int wid  = tid >> 5;
    const int wm   = wid >> 1;
    const int wn   = wid & 1;
    const int gid  = lane >> 2;
    const int tig  = lane & 3;

    const int row0 = blockIdx.x << 7;
    const int col0 = blockIdx.y << 7;
    const int hh   = col0 >> 7;

    const int a_row = (lane & 15);
    const int a_col = ((lane >> 4) << 3);
    const int b_key = (lane & 7) + ((lane >> 4) << 3);
    const int b_ecol = (((lane >> 3) & 1) << 3);

    copy16_async(g_x16 + (size_t)row0 * 64, sb, QM_X, 128, tid, 256);
    copy16_async(g_wq16 + (size_t)col0 * 64, sb, QM_W0, 128, tid, 256);
    CP_COMMIT;                                    // G0: X + Wq
    copy16_async(g_wk16 + (size_t)col0 * 64, sb, QM_W1, 128, tid, 256);
    CP_COMMIT;                                    // G1: Wk

    #pragma unroll
    for (int which = 0; which < 3; which++) {
        if (which < 2) { CP_WAIT1; } else { CP_WAIT0; }
        __syncthreads();
        const int pW = (which & 1) ? QM_W1 : QM_W0;

        float acc[2][8][4] = {};
        #pragma unroll
        for (int k = 0; k < 8; k++) {
            unsigned ah[2][4];
            #pragma unroll
            for (int mf = 0; mf < 2; mf++) {
                unsigned ao = (unsigned)((wm * 32 + mf * 16 + a_row) * 272 + (k * 16 + a_col) * 2);
                ldsm4(ah[mf], sb + QM_X + ao);
            }
            #pragma unroll
            for (int ng = 0; ng < 4; ng++) {
                unsigned bo = (unsigned)((wn * 64 + ng * 16 + b_key) * 272 + (k * 16 + b_ecol) * 2);
                unsigned bh4[4];
                ldsm4(bh4, sb + pW + bo);
                #pragma unroll
                for (int mf = 0; mf < 2; mf++) {
                    mma_f16(acc[mf][2*ng],   ah[mf], bh4[0], bh4[1]);
                    mma_f16(acc[mf][2*ng+1], ah[mf], bh4[2], bh4[3]);
                }
            }
        }
        __syncthreads();        // all warps done reading pW
        if (which == 0) {       // Wv -> buf0 (freed by the sync above)
            copy16_async(g_wv16 + (size_t)col0 * 64, sb, QM_W0, 128, tid, 256);
            CP_COMMIT;          // G2: Wv
        }

        const float* bias = (which == 0) ? bq : (which == 1) ? bk : bv;
        unsigned* dst = (which == 0) ? g_q16 : (which == 1) ? g_k16 : g_v16;
        const float sc = (which == 0) ? QSCALE_ : 1.0f;
        #pragma unroll
        for (int mf = 0; mf < 2; mf++) {
            const int lr0 = wm * 32 + mf * 16 + gid;
            #pragma unroll
            for (int nf = 0; nf < 8; nf++) {
                const int cb = wn * 64 + nf * 8 + 2 * tig;
                const float b0v = bias[col0 + cb], b1v = bias[col0 + cb + 1];
                float v0 = (acc[mf][nf][0] + b0v) * sc;
                float v1 = (acc[mf][nf][1] + b1v) * sc;
                float v2 = (acc[mf][nf][2] + b0v) * sc;
                float v3 = (acc[mf][nf][3] + b1v) * sc;
                int rw = row0 + lr0;
                int b = rw >> 9, n = rw & 511;
                dst[(((size_t)(b * H_ + hh) * N_ + n) << 6) + (cb >> 1)] = pack_h2(v0, v1);
                rw += 8; b = rw >> 9; n = rw & 511;
                dst[(((size_t)(b * H_ + hh) * N_ + n) << 6) + (cb >> 1)] = pack_h2(v2, v3);
            }
        }
    }
}

// ---------------------------------------------------------------------------
// Kernel 2: flash attention (unchanged from R15).
// ---------------------------------------------------------------------------
#define AQ_OFF    0
#define AK0_OFF   17408
#define AV0_OFF   34816
#define AD0_OFF   52224
#define AK1_OFF   61440
#define AV1_OFF   78848
#define AD1_OFF   96256
#define SMEM_ATTN 105472

__global__ __launch_bounds__(128, 2) void attn_mma_kernel()
{
    extern __shared__ char smc[];
    const unsigned sb = smem_u32(smc);

    const int tid  = threadIdx.x;
    const int lane = tid & 31;
    const int w    = tid >> 5;
    const int gid  = lane >> 2;
    const int tig  = lane & 3;

    const int q0 = blockIdx.x << 6;
    const int bh = blockIdx.y;
    const int b  = bh >> 3;

    auto loadKVD = [&](int kt, int kOff, int vOff, int dOff) {
        const size_t nb = ((size_t)bh * N_ + kt * 64) << 6;
        copy16_async(g_k16 + nb, sb, kOff, 64, tid, 128);
        copy16_async(g_v16 + nb, sb, vOff, 64, tid, 128);
        const unsigned* dsrc = g_d16 + ((size_t)b * N_ + q0) * 256 + kt * 32;
        #pragma unroll
        for (int i = 0; i < 4; i++) {
            int idx = tid + (i << 7);
            int r = idx >> 3, c = idx & 7;
            CP16(sb + dOff + r * 144 + c * 16, dsrc + (size_t)r * 256 + c * 4);
        }
    };

    copy16_async(g_q16 + (((size_t)bh * N_ + q0) << 6), sb, AQ_OFF, 64, tid, 128);
    loadKVD(0, AK0_OFF, AV0_OFF, AD0_OFF);
    CP_COMMIT;
    loadKVD(1, AK1_OFF, AV1_OFF, AD1_OFF);
    CP_COMMIT;

    float o[16][4] = {};
    float m0 = -3.0e38f, m1 = -3.0e38f, l0 = 0.f, l1 = 0.f;

    const int a_row = (lane & 15);
    const int a_col = ((lane >> 4) << 3);
    const int b_key = (lane & 7) + ((lane >> 4) << 3);
    const int b_ecol = (((lane >> 3) & 1) << 3);
    const int v_key = (lane & 7) + (((lane >> 3) & 1) << 3);
    const int v_ecol = ((lane >> 4) << 3);

    const int r0 = w * 16 + gid;
    const int r1 = r0 + 8;

    for (int kt = 0; kt < 8; kt++) {
        if (kt == 7) { CP_WAIT0; } else { CP_WAIT1; }
        __syncthreads();

        const int pK = (kt & 1) ? AK1_OFF : AK0_OFF;
        const int pV = (kt & 1) ? AV1_OFF : AV0_OFF;
        const int pD = (kt & 1) ? AD1_OFF : AD0_OFF;

        float acc[8][4];
        #pragma unroll
        for (int nf = 0; nf < 8; nf++) {
            const int c = nf * 8 + 2 * tig;
            unsigned du0 = *(const unsigned*)(smc + pD + r0 * 144 + c * 2);
            unsigned du1 = *(const unsigned*)(smc + pD + r1 * 144 + c * 2);
            float2 d0 = __half22float2(*(__half2*)&du0);
            float2 d1 = __half22float2(*(__half2*)&du1);
            acc[nf][0] = d0.x; acc[nf][1] = d0.y;
            acc[nf][2] = d1.x; acc[nf][3] = d1.y;
        }

        #pragma unroll
        for (int ks = 0; ks < 8; ks++) {
            unsigned aq[4];
            ldsm4(aq, sb + AQ_OFF + (unsigned)((w * 16 + a_row) * 272 + (ks * 16 + a_col) * 2));
            #pragma unroll
            for (int ng = 0; ng < 4; ng++) {
                unsigned bk4[4];
                ldsm4(bk4, sb + pK + (unsigned)((ng * 16 + b_key) * 272 + (ks * 16 + b_ecol) * 2));
                mma_f16(acc[2*ng],   aq, bk4[0], bk4[1]);
                mma_f16(acc[2*ng+1], aq, bk4[2], bk4[3]);
            }
        }

        float mx0 = -3.0e38f, mx1 = -3.0e38f;
        #pragma unroll
        for (int nf = 0; nf < 8; nf++) {
            mx0 = fmaxf(mx0, fmaxf(acc[nf][0], acc[nf][1]));
            mx1 = fmaxf(mx1, fmaxf(acc[nf][2], acc[nf][3]));
        }
        mx0 = fmaxf(mx0, __shfl_xor_sync(0xffffffffu, mx0, 1));
        mx0 = fmaxf(mx0, __shfl_xor_sync(0xffffffffu, mx0, 2));
        mx1 = fmaxf(mx1, __shfl_xor_sync(0xffffffffu, mx1, 1));
        mx1 = fmaxf(mx1, __shfl_xor_sync(0xffffffffu, mx1, 2));

        const float mn0 = fmaxf(m0, mx0), mn1 = fmaxf(m1, mx1);
        const float al0 = ex2f(m0 - mn0), al1 = ex2f(m1 - mn1);

        unsigned pa[4][4];
        float rs0 = 0.f, rs1 = 0.f;
        #pragma unroll
        for (int ks = 0; ks < 4; ks++) {
            float p0 = ex2f(acc[2*ks][0] - mn0);
            float p1 = ex2f(acc[2*ks][1] - mn0);
            float p2 = ex2f(acc[2*ks][2] - mn1);
            float p3 = ex2f(acc[2*ks][3] - mn1);
            float p4 = ex2f(acc[2*ks+1][0] - mn0);
            float p5 = ex2f(acc[2*ks+1][1] - mn0);
            float p6 = ex2f(acc[2*ks+1][2] - mn1);
            float p7 = ex2f(acc[2*ks+1][3] - mn1);
            rs0 += (p0 + p1) + (p4 + p5);
            rs1 += (p2 + p3) + (p6 + p7);
            pa[ks][0] = pack_h2(p0, p1);
            pa[ks][1] = pack_h2(p2, p3);
            pa[ks][2] = pack_h2(p4, p5);
            pa[ks][3] = pack_h2(p6, p7);
        }
        rs0 += __shfl_xor_sync(0xffffffffu, rs0, 1);
        rs0 += __shfl_xor_sync(0xffffffffu, rs0, 2);
        rs1 += __shfl_xor_sync(0xffffffffu, rs1, 1);
        rs1 += __shfl_xor_sync(0xffffffffu, rs1, 2);
        l0 = al0 * l0 + rs0;  l1 = al1 * l1 + rs1;
        m0 = mn0;             m1 = mn1;

        #pragma unroll
        for (int nf = 0; nf < 16; nf++) {
            o[nf][0] *= al0; o[nf][1] *= al0;
            o[nf][2] *= al1; o[nf][3] *= al1;
        }

        #pragma unroll
        for (int ks = 0; ks < 4; ks++) {
            #pragma unroll
            for (int ng = 0; ng < 8; ng++) {
                unsigned vh4[4];
                ldsm4t(vh4, sb + pV + (unsigned)((ks * 16 + v_key) * 272 + (ng * 16 + v_ecol) * 2));
                mma_f16(o[2*ng],   pa[ks], vh4[0], vh4[1]);
                mma_f16(o[2*ng+1], pa[ks], vh4[2], vh4[3]);
            }
        }
        __syncthreads();

        if (kt < 6) {
            loadKVD(kt + 2, pK, pV, pD);
            CP_COMMIT;
        }
    }

    const float li0 = 1.f / l0, li1 = 1.f / l1;
    unsigned* Y = g_y16 + (((size_t)bh * N_ + q0) << 6);
    #pragma unroll
    for (int nf = 0; nf < 16; nf++) {
        const int e = nf * 8 + 2 * tig;
        Y[(size_t)r0 * 64 + (e >> 1)] = pack_h2(o[nf][0] * li0, o[nf][1] * li0);
        Y[(size_t)r1 * 64 + (e >> 1)] = pack_h2(o[nf][2] * li1, o[nf][3] * li1);
    }
}

// ---------------------------------------------------------------------------
// Kernel 3: out = Y @ Wo^T + bo, * mask. 32x64 tiles, 512 CTAs fully
// resident (4 CTAs/SM), double-buffered h-loop.
// ---------------------------------------------------------------------------
#define OP_A0 0
#define OP_B0 8704
#define OP_A1 26112
#define OP_B1 34816
#define SMEM_OPROJ 52224

__global__ __launch_bounds__(256, 4) void oproj_mma_kernel(
    const float* __restrict__ bo,
    const float* __restrict__ mask, float* __restrict__ out)
{
    extern __shared__ char smc[];
    const unsigned sb = smem_u32(smc);

    const int tid  = threadIdx.x;
    const int lane = tid & 31;
    const int wid  = tid >> 5;
    const int wm   = wid >> 2;          // 0..1 -> 16 rows
    const int wn   = wid & 3;           // 0..3 -> 16 cols
    const int gid  = lane >> 2;
    const int tig  = lane & 3;

    const int row0 = blockIdx.x << 5;   // 256 row blocks of 32
    const int col0 = blockIdx.y << 6;   // 2 col blocks of 64
    const int b    = row0 >> 9;
    const int n0   = row0 & 511;

    const int a_row = (lane & 15);
    const int a_col = ((lane >> 4) << 3);
    const int b_key = (lane & 7) + ((lane >> 4) << 3);
    const int b_ecol = (((lane >> 3) & 1) << 3);

    auto loadAB = [&](int h, int aOff, int bOff) {
        const size_t ab = ((size_t)(b * H_ + h) * N_ + n0) << 6;
        copy16_async(g_y16 + ab, sb, aOff, 32, tid, 256);
        for (int idx = tid; idx < 1024; idx += 256) {
            int r = idx >> 4, c = idx & 15;
            size_t su = (size_t)(col0 + r) * 512 + h * 64 + c * 4;
            CP16(sb + bOff + r * 272 + c * 16, g_wo16 + su);
        }
    };

    float acc[2][4] = {};

    loadAB(0, OP_A0, OP_B0);
    CP_COMMIT;

    for (int h = 0; h < 8; h++) {
        const int pA = (h & 1) ? OP_A1 : OP_A0;
        const int pB = (h & 1) ? OP_B1 : OP_B0;
        if (h < 7) {
            loadAB(h + 1, (h & 1) ? OP_A0 : OP_A1, (h & 1) ? OP_B0 : OP_B1);
            CP_COMMIT;
            CP_WAIT1;
        } else {
            CP_WAIT0;
        }
        __syncthreads();

        #pragma unroll
        for (int k = 0; k < 8; k++) {
            unsigned ah[4];
            unsigned ao = (unsigned)((wm * 16 + a_row) * 272 + (k * 16 + a_col) * 2);
            ldsm4(ah, sb + pA + ao);
            unsigned bo_ = (unsigned)((wn * 16 + b_key) * 272 + (k * 16 + b_ecol) * 2);
            unsigned bh4[4];
            ldsm4(bh4, sb + pB + bo_);
            mma_f16(acc[0], ah, bh4[0], bh4[1]);
            mma_f16(acc[1], ah, bh4[2], bh4[3]);
        }
        __syncthreads();
    }

    const int lr0 = wm * 16 + gid;
    const int rw0 = row0 + lr0;
    const float mv0 = mask[b * 512 + (rw0 & 511)];
    const float mv1 = mask[b * 512 + ((rw0 + 8) & 511)];
    #pragma unroll
    for (int nf = 0; nf < 2; nf++) {
        const int cb = col0 + wn * 16 + nf * 8 + 2 * tig;
        const float b0v = bo[cb], b1v = bo[cb + 1];
        *(float2*)&out[(size_t)rw0 * E_ + cb] =
            make_float2((acc[nf][0] + b0v) * mv0, (acc[nf][1] + b1v) * mv0);
        *(float2*)&out[(size_t)(rw0 + 8) * E_ + cb] =
            make_float2((acc[nf][2] + b0v) * mv1, (acc[nf][3] + b1v) * mv1);
    }
}

// ---------------------------------------------------------------------------
extern "C" void kernel_launch(void* const* d_in, const int* in_sizes, int n_in,
                              void* d_out, int out_size)
{
    const float* x    = (const float*)d_in[0];
    const float* dist = (const float*)d_in[1];
    const float* mask = (const float*)d_in[2];
    const float* Wq   = (const float*)d_in[3];
    const float* bq   = (const float*)d_in[4];
    const float* Wk   = (const float*)d_in[5];
    const float* bk   = (const float*)d_in[6];
    const float* Wv   = (const float*)d_in[7];
    const float* bv   = (const float*)d_in[8];
    const float* Wo   = (const float*)d_in[9];
    const float* bo   = (const float*)d_in[10];
    float* out = (float*)d_out;

    cudaFuncSetAttribute(qkv_mma_kernel,
                         cudaFuncAttributeMaxDynamicSharedMemorySize, SMEM_QKV);
    cudaFuncSetAttribute(attn_mma_kernel,
                         cudaFuncAttributeMaxDynamicSharedMemorySize, SMEM_ATTN);
    cudaFuncSetAttribute(oproj_mma_kernel,
                         cudaFuncAttributeMaxDynamicSharedMemorySize, SMEM_OPROJ);

    prep_kernel<<<512, 256>>>(x, Wq, Wk, Wv, Wo, dist, mask);
    qkv_mma_kernel<<<dim3(64, 8), 256, SMEM_QKV>>>(bq, bk, bv);
    attn_mma_kernel<<<dim3(8, 128), 128, SMEM_ATTN>>>();
    oproj_mma_kernel<<<dim3(256, 2), 256, SMEM_OPROJ>>>(bo, mask, out);
}

// round 17
// speedup vs baseline: 1.0888x; 1.0888x over previous
#include <cuda_runtime.h>
#include <cuda_bf16.h>
#include <cuda_fp16.h>
#include <math.h>

#define B_ 16
#define N_ 512
#define H_ 8
#define E_ 128
#define BH_ (B_*H_)
#define SCALE_ 0.08838834764831845f
#define LOG2E_ 1.4426950408889634f
#define QSCALE_ (SCALE_ * LOG2E_)
#define DNEG_ (-30000.0f)

// fp16 packed (u32 = h2) arrays
__device__ unsigned g_x16[B_*N_*E_/2];
__device__ unsigned g_wq16[1024*E_/2];
__device__ unsigned g_wk16[1024*E_/2];
__device__ unsigned g_wv16[1024*E_/2];
__device__ unsigned g_wo16[E_*1024/2];
__device__ unsigned g_q16[BH_*N_*E_/2];
__device__ unsigned g_k16[BH_*N_*E_/2];
__device__ unsigned g_v16[BH_*N_*E_/2];
__device__ unsigned g_y16[BH_*N_*E_/2];
__device__ unsigned g_d16[B_*N_*N_/2];

// ---------------------------------------------------------------------------
// helpers
// ---------------------------------------------------------------------------
__device__ __forceinline__ unsigned smem_u32(const void* p) {
    unsigned r;
    asm("{ .reg .u64 t; cvta.to.shared.u64 t, %1; cvt.u32.u64 %0, t; }" : "=r"(r) : "l"(p));
    return r;
}
__device__ __forceinline__ void ldsm4(unsigned r[4], unsigned addr) {
    asm volatile("ldmatrix.sync.aligned.m8n8.x4.shared.b16 {%0,%1,%2,%3}, [%4];"
        : "=r"(r[0]), "=r"(r[1]), "=r"(r[2]), "=r"(r[3]) : "r"(addr));
}
__device__ __forceinline__ void ldsm4t(unsigned r[4], unsigned addr) {
    asm volatile("ldmatrix.sync.aligned.m8n8.x4.trans.shared.b16 {%0,%1,%2,%3}, [%4];"
        : "=r"(r[0]), "=r"(r[1]), "=r"(r[2]), "=r"(r[3]) : "r"(addr));
}
__device__ __forceinline__ void mma_f16(float c[4], const unsigned a[4],
                                        unsigned b0, unsigned b1) {
    asm volatile("mma.sync.aligned.m16n8k16.row.col.f32.f16.f16.f32 "
        "{%0,%1,%2,%3}, {%4,%5,%6,%7}, {%8,%9}, {%0,%1,%2,%3};"
        : "+f"(c[0]), "+f"(c[1]), "+f"(c[2]), "+f"(c[3])
        : "r"(a[0]), "r"(a[1]), "r"(a[2]), "r"(a[3]), "r"(b0), "r"(b1));
}
__device__ __forceinline__ unsigned pack_h2(float a, float b) {
    __half2 h = __floats2half2_rn(a, b);
    return *(unsigned*)&h;
}
__device__ __forceinline__ float ex2f(float x) {
    float r;
    asm("ex2.approx.f32 %0, %1;" : "=f"(r) : "f"(x));
    return r;
}

#define CP16(dst, src) \
    asm volatile("cp.async.cg.shared.global [%0], [%1], 16;" \
        :: "r"(dst), "l"(__cvta_generic_to_global(src)) : "memory")
#define CP_COMMIT asm volatile("cp.async.commit_group;" ::: "memory")
#define CP_WAIT0  asm volatile("cp.async.wait_group 0;" ::: "memory")
#define CP_WAIT1  asm volatile("cp.async.wait_group 1;" ::: "memory")

// packed-fp16 tile async copy: global (row stride 64 u32) -> smem 272B stride
__device__ __forceinline__ void copy16_async(const unsigned* __restrict__ src,
        unsigned sb, int off, int rows, int tid, int nthr)
{
    const int total = rows * 16;
    for (int idx = tid; idx < total; idx += nthr) {
        int r = idx >> 4, c = idx & 15;
        CP16(sb + off + r * 272 + c * 16, src + (size_t)r * 64 + c * 4);
    }
}

// ---------------------------------------------------------------------------
// Kernel 0: convert all fp32 inputs to fp16 (R15 version).
// ---------------------------------------------------------------------------
__global__ __launch_bounds__(256) void prep_kernel(
    const float* __restrict__ x,
    const float* __restrict__ Wq, const float* __restrict__ Wk,
    const float* __restrict__ Wv, const float* __restrict__ Wo,
    const float* __restrict__ dist, const float* __restrict__ mask)
{
    const int flat = blockIdx.x * 256 + threadIdx.x;

    #pragma unroll
    for (int j = 0; j < 4; j++) {
        int i = flat + j * 131072;
        float2 v = *(const float2*)(x + 2 * (size_t)i);
        g_x16[i] = pack_h2(v.x, v.y);
    }
    if (flat < 65536) {
        float2 vq = *(const float2*)(Wq + 2 * flat);
        float2 vk = *(const float2*)(Wk + 2 * flat);
        float2 vv = *(const float2*)(Wv + 2 * flat);
        float2 vo = *(const float2*)(Wo + 2 * flat);
        g_wq16[flat] = pack_h2(vq.x, vq.y);
        g_wk16[flat] = pack_h2(vk.x, vk.y);
        g_wv16[flat] = pack_h2(vv.x, vv.y);
        g_wo16[flat] = pack_h2(vo.x, vo.y);
    }
    #pragma unroll
    for (int j = 0; j < 16; j++) {
        int i = flat + j * 131072;
        float2 v = *(const float2*)(dist + 2 * (size_t)i);
        int k0 = (2 * i) & 511;
        int row = i >> 8;
        int b = row >> 9;
        float m0 = mask[b * 512 + k0], m1 = mask[b * 512 + k0 + 1];
        g_d16[i] = pack_h2((m0 != 0.f) ? v.x * LOG2E_ : DNEG_,
                           (m1 != 0.f) ? v.y * LOG2E_ : DNEG_);
    }
}

// ---------------------------------------------------------------------------
// Kernel 1: QKV projection, pure fp16 GEMM (R15 version: 3 z-slices).
// ---------------------------------------------------------------------------
#define QG_X 0
#define QG_W 34816
#define SMEM_QKV 69632

__global__ __launch_bounds__(256, 2) void qkv_mma_kernel(
    const float* __restrict__ bq, const float* __restrict__ bk,
    const float* __restrict__ bv)
{
    extern __shared__ char smc[];
    const unsigned sb = smem_u32(smc);

    const int which = blockIdx.z;
    const unsigned* __restrict__ Wsel =
        (which == 0) ? g_wq16 : (which == 1) ? g_wk16 : g_wv16;
    const float* __restrict__ bias = (which == 0) ? bq : (which == 1) ? bk : bv;
    unsigned* __restrict__ dst = (which == 0) ? g_q16 : (which == 1) ? g_k16 : g_v16;

    const int tid  = threadIdx.x;
    const int lane = tid & 31;
    const int wid  = tid >> 5;
    const int wm   = wid >> 1;
    const int wn   = wid & 1;
    const int gid  = lane >> 2;
    const int tig  = lane & 3;

    const int row0 = blockIdx.x << 7;
    const int col0 = blockIdx.y << 7;

    const int a_row = (lane & 15);
    const int a_col = ((lane >> 4) << 3);
    const int b_key = (lane & 7) + ((lane >> 4) << 3);
    const int b_ecol = (((lane >> 3) & 1) << 3);

    copy16_async(g_x16 + (size_t)row0 * 64, sb, QG_X, 128, tid, 256);
    copy16_async(Wsel + (size_t)col0 * 64, sb, QG_W, 128, tid, 256);
    CP_COMMIT; CP_WAIT0;
    __syncthreads();

    float acc[2][8][4] = {};
    #pragma unroll
    for (int k = 0; k < 8; k++) {
        unsigned ah[2][4];
        #pragma unroll
        for (int mf = 0; mf < 2; mf++) {
            unsigned ao = (unsigned)((wm * 32 + mf * 16 + a_row) * 272 + (k * 16 + a_col) * 2);
            ldsm4(ah[mf], sb + QG_X + ao);
        }
        #pragma unroll
        for (int ng = 0; ng < 4; ng++) {
            unsigned bo = (unsigned)((wn * 64 + ng * 16 + b_key) * 272 + (k * 16 + b_ecol) * 2);
            unsigned bh4[4];
            ldsm4(bh4, sb + QG_W + bo);
            #pragma unroll
            for (int mf = 0; mf < 2; mf++) {
                mma_f16(acc[mf][2*ng],   ah[mf], bh4[0], bh4[1]);
                mma_f16(acc[mf][2*ng+1], ah[mf], bh4[2], bh4[3]);
            }
        }
    }

    const int hh = col0 >> 7;
    const float sc = (which == 0) ? QSCALE_ : 1.0f;
    #pragma unroll
    for (int mf = 0; mf < 2; mf++) {
        const int lr0 = wm * 32 + mf * 16 + gid;
        #pragma unroll
        for (int nf = 0; nf < 8; nf++) {
            const int cb = wn * 64 + nf * 8 + 2 * tig;
            const float b0v = bias[col0 + cb], b1v = bias[col0 + cb + 1];
            float v0 = (acc[mf][nf][0] + b0v) * sc;
            float v1 = (acc[mf][nf][1] + b1v) * sc;
            float v2 = (acc[mf][nf][2] + b0v) * sc;
            float v3 = (acc[mf][nf][3] + b1v) * sc;
            int rw = row0 + lr0;
            int b = rw >> 9, n = rw & 511;
            dst[(((size_t)(b * H_ + hh) * N_ + n) << 6) + (cb >> 1)] = pack_h2(v0, v1);
            rw += 8; b = rw >> 9; n = rw & 511;
            dst[(((size_t)(b * H_ + hh) * N_ + n) << 6) + (cb >> 1)] = pack_h2(v2, v3);
        }
    }
}

// ---------------------------------------------------------------------------
// Kernel 2: flash attention (R15 + Q fragments hoisted out of the kt loop).
// ---------------------------------------------------------------------------
#define AQ_OFF    0
#define AK0_OFF   17408
#define AV0_OFF   34816
#define AD0_OFF   52224
#define AK1_OFF   61440
#define AV1_OFF   78848
#define AD1_OFF   96256
#define SMEM_ATTN 105472

__global__ __launch_bounds__(128, 2) void attn_mma_kernel()
{
    extern __shared__ char smc[];
    const unsigned sb = smem_u32(smc);

    const int tid  = threadIdx.x;
    const int lane = tid & 31;
    const int w    = tid >> 5;
    const int gid  = lane >> 2;
    const int tig  = lane & 3;

    const int q0 = blockIdx.x << 6;
    const int bh = blockIdx.y;
    const int b  = bh >> 3;

    auto loadKVD = [&](int kt, int kOff, int vOff, int dOff) {
        const size_t nb = ((size_t)bh * N_ + kt * 64) << 6;
        copy16_async(g_k16 + nb, sb, kOff, 64, tid, 128);
        copy16_async(g_v16 + nb, sb, vOff, 64, tid, 128);
        const unsigned* dsrc = g_d16 + ((size_t)b * N_ + q0) * 256 + kt * 32;
        #pragma unroll
        for (int i = 0; i < 4; i++) {
            int idx = tid + (i << 7);
            int r = idx >> 3, c = idx & 7;
            CP16(sb + dOff + r * 144 + c * 16, dsrc + (size_t)r * 256 + c * 4);
        }
    };

    copy16_async(g_q16 + (((size_t)bh * N_ + q0) << 6), sb, AQ_OFF, 64, tid, 128);
    loadKVD(0, AK0_OFF, AV0_OFF, AD0_OFF);
    CP_COMMIT;
    loadKVD(1, AK1_OFF, AV1_OFF, AD1_OFF);
    CP_COMMIT;

    float o[16][4] = {};
    float m0 = -3.0e38f, m1 = -3.0e38f, l0 = 0.f, l1 = 0.f;

    const int a_row = (lane & 15);
    const int a_col = ((lane >> 4) << 3);
    const int b_key = (lane & 7) + ((lane >> 4) << 3);
    const int b_ecol = (((lane >> 3) & 1) << 3);
    const int v_key = (lane & 7) + (((lane >> 3) & 1) << 3);
    const int v_ecol = ((lane >> 4) << 3);

    const int r0 = w * 16 + gid;
    const int r1 = r0 + 8;

    // hoist Q fragments (invariant across all key chunks)
    unsigned qf[8][4];
    {
        CP_WAIT1;               // Q (+ chunk0) resident
        __syncthreads();
        #pragma unroll
        for (int ks = 0; ks < 8; ks++)
            ldsm4(qf[ks], sb + AQ_OFF + (unsigned)((w * 16 + a_row) * 272 + (ks * 16 + a_col) * 2));
    }

    for (int kt = 0; kt < 8; kt++) {
        if (kt == 7) { CP_WAIT0; } else { CP_WAIT1; }
        __syncthreads();

        const int pK = (kt & 1) ? AK1_OFF : AK0_OFF;
        const int pV = (kt & 1) ? AV1_OFF : AV0_OFF;
        const int pD = (kt & 1) ? AD1_OFF : AD0_OFF;

        // ---- seed S accumulators with dist (mask baked in) ----
        float acc[8][4];
        #pragma unroll
        for (int nf = 0; nf < 8; nf++) {
            const int c = nf * 8 + 2 * tig;
            unsigned du0 = *(const unsigned*)(smc + pD + r0 * 144 + c * 2);
            unsigned du1 = *(const unsigned*)(smc + pD + r1 * 144 + c * 2);
            float2 d0 = __half22float2(*(__half2*)&du0);
            float2 d1 = __half22float2(*(__half2*)&du1);
            acc[nf][0] = d0.x; acc[nf][1] = d0.y;
            acc[nf][2] = d1.x; acc[nf][3] = d1.y;
        }

        // ---- S += Q K^T ----
        #pragma unroll
        for (int ks = 0; ks < 8; ks++) {
            #pragma unroll
            for (int ng = 0; ng < 4; ng++) {
                unsigned bk4[4];
                ldsm4(bk4, sb + pK + (unsigned)((ng * 16 + b_key) * 272 + (ks * 16 + b_ecol) * 2));
                mma_f16(acc[2*ng],   qf[ks], bk4[0], bk4[1]);
                mma_f16(acc[2*ng+1], qf[ks], bk4[2], bk4[3]);
            }
        }

        // ---- row max ----
        float mx0 = -3.0e38f, mx1 = -3.0e38f;
        #pragma unroll
        for (int nf = 0; nf < 8; nf++) {
            mx0 = fmaxf(mx0, fmaxf(acc[nf][0], acc[nf][1]));
            mx1 = fmaxf(mx1, fmaxf(acc[nf][2], acc[nf][3]));
        }
        mx0 = fmaxf(mx0, __shfl_xor_sync(0xffffffffu, mx0, 1));
        mx0 = fmaxf(mx0, __shfl_xor_sync(0xffffffffu, mx0, 2));
        mx1 = fmaxf(mx1, __shfl_xor_sync(0xffffffffu, mx1, 1));
        mx1 = fmaxf(mx1, __shfl_xor_sync(0xffffffffu, mx1, 2));

        const float mn0 = fmaxf(m0, mx0), mn1 = fmaxf(m1, mx1);
        const float al0 = ex2f(m0 - mn0), al1 = ex2f(m1 - mn1);

        // ---- P = exp2(S - m) into PV A-fragments ----
        unsigned pa[4][4];
        float rs0 = 0.f, rs1 = 0.f;
        #pragma unroll
        for (int ks = 0; ks < 4; ks++) {
            float p0 = ex2f(acc[2*ks][0] - mn0);
            float p1 = ex2f(acc[2*ks][1] - mn0);
            float p2 = ex2f(acc[2*ks][2] - mn1);
            float p3 = ex2f(acc[2*ks][3] - mn1);
            float p4 = ex2f(acc[2*ks+1][0] - mn0);
            float p5 = ex2f(acc[2*ks+1][1] - mn0);
            float p6 = ex2f(acc[2*ks+1][2] - mn1);
            float p7 = ex2f(acc[2*ks+1][3] - mn1);
            rs0 += (p0 + p1) + (p4 + p5);
            rs1 += (p2 + p3) + (p6 + p7);
            pa[ks][0] = pack_h2(p0, p1);
            pa[ks][1] = pack_h2(p2, p3);
            pa[ks][2] = pack_h2(p4, p5);
            pa[ks][3] = pack_h2(p6, p7);
        }
        rs0 += __shfl_xor_sync(0xffffffffu, rs0, 1);
        rs0 += __shfl_xor_sync(0xffffffffu, rs0, 2);
        rs1 += __shfl_xor_sync(0xffffffffu, rs1, 1);
        rs1 += __shfl_xor_sync(0xffffffffu, rs1, 2);
        l0 = al0 * l0 + rs0;  l1 = al1 * l1 + rs1;
        m0 = mn0;             m1 = mn1;

        #pragma unroll
        for (int nf = 0; nf < 16; nf++) {
            o[nf][0] *= al0; o[nf][1] *= al0;
            o[nf][2] *= al1; o[nf][3] *= al1;
        }

        // ---- O += P V ----
        #pragma unroll
        for (int ks = 0; ks < 4; ks++) {
            #pragma unroll
            for (int ng = 0; ng < 8; ng++) {
                unsigned vh4[4];
                ldsm4t(vh4, sb + pV + (unsigned)((ks * 16 + v_key) * 272 + (ng * 16 + v_ecol) * 2));
                mma_f16(o[2*ng],   pa[ks], vh4[0], vh4[1]);
                mma_f16(o[2*ng+1], pa[ks], vh4[2], vh4[3]);
            }
        }
        __syncthreads();

        if (kt < 6) {
            loadKVD(kt + 2, pK, pV, pD);
            CP_COMMIT;
        }
    }

    const float li0 = 1.f / l0, li1 = 1.f / l1;
    unsigned* Y = g_y16 + (((size_t)bh * N_ + q0) << 6);
    #pragma unroll
    for (int nf = 0; nf < 16; nf++) {
        const int e = nf * 8 + 2 * tig;
        Y[(size_t)r0 * 64 + (e >> 1)] = pack_h2(o[nf][0] * li0, o[nf][1] * li0);
        Y[(size_t)r1 * 64 + (e >> 1)] = pack_h2(o[nf][2] * li1, o[nf][3] * li1);
    }
}

// ---------------------------------------------------------------------------
// Kernel 3: out = Y @ Wo^T + bo, * mask (R15 version: 64x64 tiles,
// double-buffered h-loop, 3 CTAs/SM, grid (128,2)).
// ---------------------------------------------------------------------------
#define OG_A0 0
#define OG_B0 17408
#define OG_A1 34816
#define OG_B1 52224
#define SMEM_OPROJ 69632

__global__ __launch_bounds__(256, 3) void oproj_mma_kernel(
    const float* __restrict__ bo,
    const float* __restrict__ mask, float* __restrict__ out)
{
    extern __shared__ char smc[];
    const unsigned sb = smem_u32(smc);

    const int tid  = threadIdx.x;
    const int lane = tid & 31;
    const int wid  = tid >> 5;
    const int wm   = wid >> 1;
    const int wn   = wid & 1;
    const int gid  = lane >> 2;
    const int tig  = lane & 3;

    const int row0 = blockIdx.x << 6;
    const int col0 = blockIdx.y << 6;
    const int b    = row0 >> 9;
    const int n0   = row0 & 511;

    const int a_row = (lane & 15);
    const int a_col = ((lane >> 4) << 3);
    const int b_key = (lane & 7) + ((lane >> 4) << 3);
    const int b_ecol = (((lane >> 3) & 1) << 3);

    auto loadAB = [&](int h, int aOff, int bOff) {
        const size_t ab = ((size_t)(b * H_ + h) * N_ + n0) << 6;
        copy16_async(g_y16 + ab, sb, aOff, 64, tid, 256);
        for (int idx = tid; idx < 1024; idx += 256) {
            int r = idx >> 4, c = idx & 15;
            size_t su = (size_t)(col0 + r) * 512 + h * 64 + c * 4;
            CP16(sb + bOff + r * 272 + c * 16, g_wo16 + su);
        }
    };

    float acc[4][4] = {};

    loadAB(0, OG_A0, OG_B0);
    CP_COMMIT;

    for (int h = 0; h < 8; h++) {
        const int pA = (h & 1) ? OG_A1 : OG_A0;
        const int pB = (h & 1) ? OG_B1 : OG_B0;
        if (h < 7) {
            loadAB(h + 1, (h & 1) ? OG_A0 : OG_A1, (h & 1) ? OG_B0 : OG_B1);
            CP_COMMIT;
            CP_WAIT1;
        } else {
            CP_WAIT0;
        }
        __syncthreads();

        #pragma unroll
        for (int k = 0; k < 8; k++) {
            unsigned ah[4];
            unsigned ao = (unsigned)((wm * 16 + a_row) * 272 + (k * 16 + a_col) * 2);
            ldsm4(ah, sb + pA + ao);
            #pragma unroll
            for (int ng = 0; ng < 2; ng++) {
                unsigned bo_ = (unsigned)((wn * 32 + ng * 16 + b_key) * 272 + (k * 16 + b_ecol) * 2);
                unsigned bh4[4];
                ldsm4(bh4, sb + pB + bo_);
                mma_f16(acc[2*ng],   ah, bh4[0], bh4[1]);
                mma_f16(acc[2*ng+1], ah, bh4[2], bh4[3]);
            }
        }
        __syncthreads();
    }

    const int lr0 = wm * 16 + gid;
    const int rw0 = row0 + lr0;
    const float mv0 = mask[b * 512 + (rw0 & 511)];
    const float mv1 = mask[b * 512 + ((rw0 + 8) & 511)];
    #pragma unroll
    for (int nf = 0; nf < 4; nf++) {
        const int cb = col0 + wn * 32 + nf * 8 + 2 * tig;
        const float b0v = bo[cb], b1v = bo[cb + 1];
        *(float2*)&out[(size_t)rw0 * E_ + cb] =
            make_float2((acc[nf][0] + b0v) * mv0, (acc[nf][1] + b1v) * mv0);
        *(float2*)&out[(size_t)(rw0 + 8) * E_ + cb] =
            make_float2((acc[nf][2] + b0v) * mv1, (acc[nf][3] + b1v) * mv1);
    }
}

// ---------------------------------------------------------------------------
extern "C" void kernel_launch(void* const* d_in, const int* in_sizes, int n_in,
                              void* d_out, int out_size)
{
    const float* x    = (const float*)d_in[0];
    const float* dist = (const float*)d_in[1];
    const float* mask = (const float*)d_in[2];
    const float* Wq   = (const float*)d_in[3];
    const float* bq   = (const float*)d_in[4];
    const float* Wk   = (const float*)d_in[5];
    const float* bk   = (const float*)d_in[6];
    const float* Wv   = (const float*)d_in[7];
    const float* bv   = (const float*)d_in[8];
    const float* Wo   = (const float*)d_in[9];
    const float* bo   = (const float*)d_in[10];
    float* out = (float*)d_out;

    cudaFuncSetAttribute(qkv_mma_kernel,
                         cudaFuncAttributeMaxDynamicSharedMemorySize, SMEM_QKV);
    cudaFuncSetAttribute(attn_mma_kernel,
                         cudaFuncAttributeMaxDynamicSharedMemorySize, SMEM_ATTN);
    cudaFuncSetAttribute(oproj_mma_kernel,
                         cudaFuncAttributeMaxDynamicSharedMemorySize, SMEM_OPROJ);

    prep_kernel<<<512, 256>>>(x, Wq, Wk, Wv, Wo, dist, mask);
    qkv_mma_kernel<<<dim3(64, 8, 3), 256, SMEM_QKV>>>(bq, bk, bv);
    attn_mma_kernel<<<dim3(8, 128), 128, SMEM_ATTN>>>();
    oproj_mma_kernel<<<dim3(128, 2), 256, SMEM_OPROJ>>>(bo, mask, out);
}